// round 1
// baseline (speedup 1.0000x reference)
#include <cuda_runtime.h>

// Problem constants
#define B_    4
#define N_    512
#define T_    10
#define F_    516      // N + 4
#define HID   128
#define MSGD  32
#define UPDH  128
#define OUTD  4

// Tiling for the main edge kernel
#define ITILE  8                 // i's per CTA (one warp per i)
#define JSPLIT 2                 // split of the j loop across CTAs
#define JCHUNK (N_ / JSPLIT)     // 256 j per CTA

// Scratch (static device arrays: no allocations allowed)
__device__ float g_C[B_ * N_ * HID];                 // C[b,j,hid] with mb1 folded in
__device__ float g_part[JSPLIT * B_ * N_ * HID];     // partial H_sum per j-split

// ---------------------------------------------------------------------------
// packed fp32x2 FMA (sm_100+)
// ---------------------------------------------------------------------------
__device__ __forceinline__ float2 ffma2(float2 a, float2 b, float2 c) {
    float2 d;
    asm("fma.rn.f32x2 %0, %1, %2, %3;"
        : "=l"(reinterpret_cast<unsigned long long&>(d))
        : "l"(reinterpret_cast<unsigned long long&>(a)),
          "l"(reinterpret_cast<unsigned long long&>(b)),
          "l"(reinterpret_cast<unsigned long long&>(c)));
    return d;
}

// ---------------------------------------------------------------------------
// Kernel A: C[b,j,hid] = mb1[hid] + sum_{t,k<4} x[b,j,t,k] * mW1[5t+k, hid]
// grid: B*N blocks, 128 threads (one per hid)
// ---------------------------------------------------------------------------
__global__ __launch_bounds__(128) void kA(const float* __restrict__ x,
                                          const float* __restrict__ mW1,
                                          const float* __restrict__ mb1) {
    const int bj  = blockIdx.x;       // b*N + j
    const int hid = threadIdx.x;

    __shared__ float sb[T_ * 4];
    if (hid < T_ * 4) {
        const int t = hid >> 2, k = hid & 3;
        sb[hid] = x[((long)bj * T_ + t) * F_ + k];
    }
    __syncthreads();

    float acc = mb1[hid];
#pragma unroll
    for (int t = 0; t < T_; ++t) {
#pragma unroll
        for (int k = 0; k < 4; ++k) {
            acc = fmaf(sb[t * 4 + k], mW1[(5 * t + k) * HID + hid], acc);
        }
    }
    g_C[(long)bj * HID + hid] = acc;
}

// ---------------------------------------------------------------------------
// Kernel B (dominant): for each (b, i): H_sum[b,i,:] = sum_j relu(C[b,j,:] +
//                       sum_t extra[b,j,t,i] * w_t[:])
// where w_t = mW1[5t+4, :]. One CTA = (itile of 8 i, b, j-half).
// 256 threads: warp = one i; thread owns 4 consecutive hidden units.
// Double-buffered smem, prefetch distance 2, packed f32x2 math.
// e values are stored DUPLICATED in smem ({e,e} float2) so LDS.128 delivers
// ready f32x2 multiplicands with no packing MOVs.
// ---------------------------------------------------------------------------
__global__ __launch_bounds__(256) void kB(const float* __restrict__ x,
                                          const float* __restrict__ mW1) {
    const int tid    = threadIdx.x;
    const int itile  = blockIdx.x;            // 0..63
    const int b      = blockIdx.y;            // 0..3
    const int js     = blockIdx.z;            // 0..JSPLIT-1
    const int iglob0 = itile * ITILE;
    const int i_loc  = tid >> 5;              // 0..7  (warp id = local i)
    const int hid0   = (tid & 31) * 4;        // 4 hidden units per thread

    // Per-thread weight slice: w_t for hid0..hid0+3, as two f32x2 each
    float2 w0[T_], w1[T_];
#pragma unroll
    for (int t = 0; t < T_; ++t) {
        float4 w = *reinterpret_cast<const float4*>(&mW1[(5 * t + 4) * HID + hid0]);
        w0[t] = make_float2(w.x, w.y);
        w1[t] = make_float2(w.z, w.w);
    }

    __shared__ __align__(16) float2 e_s[2][ITILE][T_];   // duplicated {e,e}
    __shared__ __align__(16) float  c_s[2][HID];

    const int  j0   = js * JCHUNK;
    const bool is_e = (tid < ITILE * T_);                              // 80 loaders
    const bool is_c = (tid >= ITILE * T_) && (tid < ITILE * T_ + HID); // 128 loaders
    const int  el_i = tid & (ITILE - 1);
    const int  el_t = tid >> 3;                                        // ITILE==8
    const int  c_h  = tid - ITILE * T_;

    const float* eg = x + ((long)(b * N_ + j0) * T_ + el_t) * F_ + 4 + iglob0 + el_i;
    const float* cg = g_C + (long)(b * N_ + j0) * HID + c_h;
    const long   estr = (long)T_ * F_;   // x stride per j

    // Prologue: load j0 (vA) and j0+1 (vB); stage j0 into buffer 0
    float vA = 0.f, vB = 0.f;
    if (is_e)      { vA = eg[0]; vB = eg[estr]; }
    else if (is_c) { vA = cg[0]; vB = cg[HID];  }
    if (is_e)      e_s[0][el_i][el_t] = make_float2(vA, vA);
    else if (is_c) c_s[0][c_h] = vA;
    __syncthreads();

    float a0 = 0.f, a1 = 0.f, a2 = 0.f, a3 = 0.f;

    for (int jj = 0; jj < JCHUNK; ++jj) {
        const int cur = jj & 1, nxt = cur ^ 1;

        // prefetch j+2 into vA (latency overlapped with compute below)
        if (jj + 2 < JCHUNK) {
            if (is_e)      vA = eg[(long)(jj + 2) * estr];
            else if (is_c) vA = cg[(jj + 2) * HID];
        }

        // ---- compute edge (i, j=jj) for this thread's 4 hidden units ----
        float4 cv = *reinterpret_cast<const float4*>(&c_s[cur][hid0]);
        float2 p0 = make_float2(cv.x, cv.y);
        float2 p1 = make_float2(cv.z, cv.w);
        const float2* ep = e_s[cur][i_loc];
#pragma unroll
        for (int t = 0; t < T_; t += 2) {
            float4 ev = *reinterpret_cast<const float4*>(&ep[t]);  // {e_t,e_t,e_t1,e_t1}
            float2 ea = make_float2(ev.x, ev.y);
            float2 eb = make_float2(ev.z, ev.w);
            p0 = ffma2(ea, w0[t], p0);
            p1 = ffma2(ea, w1[t], p1);
            p0 = ffma2(eb, w0[t + 1], p0);
            p1 = ffma2(eb, w1[t + 1], p1);
        }
        a0 += fmaxf(p0.x, 0.f);
        a1 += fmaxf(p0.y, 0.f);
        a2 += fmaxf(p1.x, 0.f);
        a3 += fmaxf(p1.y, 0.f);

        __syncthreads();
        // stage j+1 (held in vB) into the other buffer
        if (jj + 1 < JCHUNK) {
            if (is_e)      e_s[nxt][el_i][el_t] = make_float2(vB, vB);
            else if (is_c) c_s[nxt][c_h] = vB;
        }
        __syncthreads();
        // rotate: vB <- (j+2 just loaded), vA free
        float tswap = vA; vA = vB; vB = tswap;
    }

    float4 r = make_float4(a0, a1, a2, a3);
    *reinterpret_cast<float4*>(
        &g_part[(((long)js * B_ + b) * N_ + (iglob0 + i_loc)) * HID + hid0]) = r;
}

// ---------------------------------------------------------------------------
// Kernel C: per node — reduce j-split partials, apply mW2 (+ N*mb2),
// concat node_feat = x[b,n,T-1,:4], then 36 -> 128 (relu) -> 4 MLP.
// grid: B*N blocks, 128 threads.
// ---------------------------------------------------------------------------
__global__ __launch_bounds__(128) void kC(const float* __restrict__ x,
                                          const float* __restrict__ mW2,
                                          const float* __restrict__ mb2,
                                          const float* __restrict__ iW1,
                                          const float* __restrict__ ib1,
                                          const float* __restrict__ iW2,
                                          const float* __restrict__ ib2,
                                          float* __restrict__ out) {
    const int node = blockIdx.x;      // b*N + n
    const int tid  = threadIdx.x;     // 0..127

    __shared__ float s_h[HID];
    __shared__ float s_mi[MSGD + 4];
    __shared__ float s_h2[UPDH];

    // reduce JSPLIT partial sums
    float h = 0.f;
#pragma unroll
    for (int p = 0; p < JSPLIT; ++p)
        h += g_part[(long)p * (B_ * N_ * HID) + (long)node * HID + tid];
    s_h[tid] = h;
    __syncthreads();

    if (tid < MSGD) {
        float acc = (float)N_ * mb2[tid];
#pragma unroll 8
        for (int k = 0; k < HID; ++k)
            acc = fmaf(s_h[k], mW2[k * MSGD + tid], acc);
        s_mi[tid] = acc;
    } else if (tid < MSGD + 4) {
        s_mi[tid] = x[((long)node * T_ + (T_ - 1)) * F_ + (tid - MSGD)];
    }
    __syncthreads();

    {
        float acc = ib1[tid];
#pragma unroll
        for (int k = 0; k < MSGD + 4; ++k)
            acc = fmaf(s_mi[k], iW1[k * UPDH + tid], acc);
        s_h2[tid] = fmaxf(acc, 0.f);
    }
    __syncthreads();

    if (tid < OUTD) {
        float acc = ib2[tid];
#pragma unroll 8
        for (int k = 0; k < UPDH; ++k)
            acc = fmaf(s_h2[k], iW2[k * OUTD + tid], acc);
        out[(long)node * OUTD + tid] = acc;
    }
}

// ---------------------------------------------------------------------------
extern "C" void kernel_launch(void* const* d_in, const int* in_sizes, int n_in,
                              void* d_out, int out_size) {
    const float* x   = (const float*)d_in[0];
    const float* mW1 = (const float*)d_in[1];
    const float* mb1 = (const float*)d_in[2];
    const float* mW2 = (const float*)d_in[3];
    const float* mb2 = (const float*)d_in[4];
    const float* iW1 = (const float*)d_in[5];
    const float* ib1 = (const float*)d_in[6];
    const float* iW2 = (const float*)d_in[7];
    const float* ib2 = (const float*)d_in[8];
    float* out = (float*)d_out;

    kA<<<B_ * N_, HID>>>(x, mW1, mb1);

    dim3 gB(N_ / ITILE, B_, JSPLIT);   // (64, 4, 2) = 512 CTAs
    kB<<<gB, 256>>>(x, mW1);

    kC<<<B_ * N_, HID>>>(x, mW2, mb2, iW1, ib1, iW2, ib2, out);
}

// round 2
// speedup vs baseline: 1.7873x; 1.7873x over previous
#include <cuda_runtime.h>

// Problem constants
#define B_    4
#define N_    512
#define T_    10
#define F_    516      // N + 4
#define HID   128
#define MSGD  32
#define UPDH  128
#define OUTD  4

// Tiling for the main edge kernel
#define ITILE  8                 // i's per CTA (one warp per i)
#define KJ     8                 // j's staged per barrier round
#define JSPLIT 4                 // split of the j loop across CTAs
#define JCHUNK (N_ / JSPLIT)     // 128 j per CTA
#define ROUNDS (JCHUNK / KJ)     // 16 rounds

// Scratch (static device arrays: no allocations allowed)
__device__ float g_C[B_ * N_ * HID];                 // C[b,j,hid], mb1 folded in
__device__ float g_part[JSPLIT * B_ * N_ * HID];     // partial H_sum per j-split

// ---------------------------------------------------------------------------
// packed fp32x2 helpers (sm_100+)
// ---------------------------------------------------------------------------
__device__ __forceinline__ float2 ffma2(float2 a, float2 b, float2 c) {
    float2 d;
    asm("fma.rn.f32x2 %0, %1, %2, %3;"
        : "=l"(reinterpret_cast<unsigned long long&>(d))
        : "l"(reinterpret_cast<unsigned long long&>(a)),
          "l"(reinterpret_cast<unsigned long long&>(b)),
          "l"(reinterpret_cast<unsigned long long&>(c)));
    return d;
}
__device__ __forceinline__ float2 fadd2(float2 a, float2 b) {
    float2 d;
    asm("add.rn.f32x2 %0, %1, %2;"
        : "=l"(reinterpret_cast<unsigned long long&>(d))
        : "l"(reinterpret_cast<unsigned long long&>(a)),
          "l"(reinterpret_cast<unsigned long long&>(b)));
    return d;
}

// ---------------------------------------------------------------------------
// Kernel A: C[b,j,hid] = mb1[hid] + sum_{t,k<4} x[b,j,t,k] * mW1[5t+k, hid]
// 256 blocks, each handles 8 (b,j); weights live in 40 registers per thread.
// ---------------------------------------------------------------------------
#define ABJ 8
__global__ __launch_bounds__(128) void kA(const float* __restrict__ x,
                                          const float* __restrict__ mW1,
                                          const float* __restrict__ mb1) {
    const int hid = threadIdx.x;
    float w[40];
#pragma unroll
    for (int r = 0; r < 40; ++r)
        w[r] = mW1[(5 * (r >> 2) + (r & 3)) * HID + hid];
    const float bias = mb1[hid];

    __shared__ float sb[ABJ][40];
    const int bj0 = blockIdx.x * ABJ;
    for (int idx = hid; idx < ABJ * 40; idx += 128) {
        const int nn = idx / 40, r = idx % 40;
        sb[nn][r] = x[((long)(bj0 + nn) * T_ + (r >> 2)) * F_ + (r & 3)];
    }
    __syncthreads();

#pragma unroll
    for (int nn = 0; nn < ABJ; ++nn) {
        float acc = bias;
#pragma unroll
        for (int r = 0; r < 40; ++r) acc = fmaf(sb[nn][r], w[r], acc);
        g_C[(long)(bj0 + nn) * HID + hid] = acc;
    }
}

// ---------------------------------------------------------------------------
// Kernel B (dominant): H_sum[b,i,:] = sum_j relu(C[b,j,:] + sum_t e[b,j,t,i]*w_t[:])
// CTA = (itile of 8 i, b, j-quarter). 256 threads; warp = one i; lane = 4 hids.
// Round-based: 8 j per single __syncthreads(); double-buffered smem; e stored
// DUPLICATED as {e,e} float2 so LDS.128 yields ready f32x2 multiplicands.
// ---------------------------------------------------------------------------
__global__ __launch_bounds__(256) void kB(const float* __restrict__ x,
                                          const float* __restrict__ mW1) {
    const int tid    = threadIdx.x;
    const int itile  = blockIdx.x;            // 0..63
    const int b      = blockIdx.y;            // 0..3
    const int js     = blockIdx.z;            // 0..JSPLIT-1
    const int iglob0 = itile * ITILE;
    const int i_loc  = tid >> 5;              // warp id = local i
    const int hid0   = (tid & 31) * 4;        // 4 hidden units per lane

    // Loop-invariant weight slice: w_t for hid0..hid0+3, as two f32x2 each
    float2 w0[T_], w1[T_];
#pragma unroll
    for (int t = 0; t < T_; ++t) {
        float4 w = *reinterpret_cast<const float4*>(&mW1[(5 * t + 4) * HID + hid0]);
        w0[t] = make_float2(w.x, w.y);
        w1[t] = make_float2(w.z, w.w);
    }

    __shared__ __align__(16) float2 e_s[2][KJ][ITILE][T_];  // duplicated {e,e}
    __shared__ __align__(16) float  c_s[2][KJ][HID];

    const int  j0   = js * JCHUNK;
    const bool is_e = (tid < ITILE * T_);                              // 80 loaders
    const bool is_c = (tid >= ITILE * T_) && (tid < ITILE * T_ + HID); // 128 loaders
    const int  el_i = tid & (ITILE - 1);
    const int  el_t = tid >> 3;                                        // ITILE==8
    const int  c_h  = tid - ITILE * T_;

    const float* eg = x + ((long)(b * N_ + j0) * T_ + el_t) * F_ + 4 + iglob0 + el_i;
    const float* cg = g_C + (long)(b * N_ + j0) * HID + c_h;
    const long   estr = (long)T_ * F_;   // x stride per j

    float rv[KJ];   // one round of staged values

    // load round r into rv
    auto loadRound = [&](int r) {
        const int jb = r * KJ;
        if (is_e) {
#pragma unroll
            for (int jj = 0; jj < KJ; ++jj) rv[jj] = eg[(long)(jb + jj) * estr];
        } else if (is_c) {
#pragma unroll
            for (int jj = 0; jj < KJ; ++jj) rv[jj] = cg[(long)(jb + jj) * HID];
        }
    };
    // store rv into buffer buf
    auto storeRound = [&](int buf) {
        if (is_e) {
#pragma unroll
            for (int jj = 0; jj < KJ; ++jj)
                e_s[buf][jj][el_i][el_t] = make_float2(rv[jj], rv[jj]);
        } else if (is_c) {
#pragma unroll
            for (int jj = 0; jj < KJ; ++jj) c_s[buf][jj][c_h] = rv[jj];
        }
    };

    // Prologue: stage round 0, preload round 1
    loadRound(0);
    storeRound(0);
    loadRound(1);
    __syncthreads();

    float2 acc01 = make_float2(0.f, 0.f);
    float2 acc23 = make_float2(0.f, 0.f);

#pragma unroll 1
    for (int r = 0; r < ROUNDS; ++r) {
        const int cur = r & 1;

        // ---- compute 8 edges (i, j in round r) ----
#pragma unroll
        for (int jj = 0; jj < KJ; ++jj) {
            float4 cv = *reinterpret_cast<const float4*>(&c_s[cur][jj][hid0]);
            float2 p0 = make_float2(cv.x, cv.y);
            float2 p1 = make_float2(cv.z, cv.w);
            const float4* ep = reinterpret_cast<const float4*>(e_s[cur][jj][i_loc]);
#pragma unroll
            for (int tt = 0; tt < T_ / 2; ++tt) {
                float4 ev = ep[tt];                     // {e,e,e',e'} broadcast
                float2 ea = make_float2(ev.x, ev.y);
                float2 eb = make_float2(ev.z, ev.w);
                p0 = ffma2(ea, w0[2 * tt], p0);
                p1 = ffma2(ea, w1[2 * tt], p1);
                p0 = ffma2(eb, w0[2 * tt + 1], p0);
                p1 = ffma2(eb, w1[2 * tt + 1], p1);
            }
            acc01 = fadd2(acc01, make_float2(fmaxf(p0.x, 0.f), fmaxf(p0.y, 0.f)));
            acc23 = fadd2(acc23, make_float2(fmaxf(p1.x, 0.f), fmaxf(p1.y, 0.f)));
        }

        // stage round r+1 (held in rv), then refill rv with round r+2
        if (r + 1 < ROUNDS) storeRound(cur ^ 1);
        if (r + 2 < ROUNDS) loadRound(r + 2);
        __syncthreads();
    }

    float4 res = make_float4(acc01.x, acc01.y, acc23.x, acc23.y);
    *reinterpret_cast<float4*>(
        &g_part[(((long)js * B_ + b) * N_ + (iglob0 + i_loc)) * HID + hid0]) = res;
}

// ---------------------------------------------------------------------------
// Kernel C: per node — reduce j-split partials, apply mW2 (+ N*mb2),
// concat node_feat, 36 -> 128 (relu) -> 4 MLP. Block = 8 nodes, weights in smem.
// ---------------------------------------------------------------------------
#define NPB 8
__global__ __launch_bounds__(128) void kC(const float* __restrict__ x,
                                          const float* __restrict__ mW2,
                                          const float* __restrict__ mb2,
                                          const float* __restrict__ iW1,
                                          const float* __restrict__ ib1,
                                          const float* __restrict__ iW2,
                                          const float* __restrict__ ib2,
                                          float* __restrict__ out) {
    const int tid = threadIdx.x;

    __shared__ float s_mW2[HID * MSGD];          // 16 KB
    __shared__ float s_iW1[(MSGD + 4) * UPDH];   // 18 KB
    __shared__ float s_iW2[UPDH * OUTD];         // 2 KB
    __shared__ float s_mb2[MSGD], s_ib1[UPDH], s_ib2[OUTD];
    __shared__ float s_h[HID];
    __shared__ float s_red[4][MSGD];
    __shared__ float s_mi[MSGD + 4];
    __shared__ float s_h2[UPDH];
    __shared__ float s_nf[NPB][4];

    for (int i = tid; i < HID * MSGD; i += 128)        s_mW2[i] = mW2[i];
    for (int i = tid; i < (MSGD + 4) * UPDH; i += 128) s_iW1[i] = iW1[i];
    for (int i = tid; i < UPDH * OUTD; i += 128)       s_iW2[i] = iW2[i];
    if (tid < MSGD) s_mb2[tid] = mb2[tid];
    s_ib1[tid] = ib1[tid];
    if (tid < OUTD) s_ib2[tid] = ib2[tid];
    if (tid < NPB * 4) {
        const int nn = tid >> 2, k = tid & 3;
        s_nf[nn][k] = x[((long)(blockIdx.x * NPB + nn) * T_ + (T_ - 1)) * F_ + k];
    }
    __syncthreads();

    for (int nn = 0; nn < NPB; ++nn) {
        const long node = (long)blockIdx.x * NPB + nn;

        float h = 0.f;
#pragma unroll
        for (int p = 0; p < JSPLIT; ++p)
            h += g_part[(long)p * (B_ * N_ * HID) + node * HID + tid];
        s_h[tid] = h;
        __syncthreads();

        {   // mW2 GEMV split 4 ways over k
            const int m = tid & 31, seg = tid >> 5;
            float a = 0.f;
#pragma unroll
            for (int k2 = 0; k2 < 32; ++k2) {
                const int k = seg * 32 + k2;
                a = fmaf(s_h[k], s_mW2[k * MSGD + m], a);
            }
            s_red[seg][m] = a;
        }
        __syncthreads();
        if (tid < MSGD)
            s_mi[tid] = s_red[0][tid] + s_red[1][tid] + s_red[2][tid] + s_red[3][tid]
                      + (float)N_ * s_mb2[tid];
        if (tid < 4) s_mi[MSGD + tid] = s_nf[nn][tid];
        __syncthreads();

        {   // 36 -> 128 relu
            float a = s_ib1[tid];
#pragma unroll
            for (int k = 0; k < MSGD + 4; ++k)
                a = fmaf(s_mi[k], s_iW1[k * UPDH + tid], a);
            s_h2[tid] = fmaxf(a, 0.f);
        }
        __syncthreads();

        {   // 128 -> 4: warp o computes output o, shuffle-reduce
            const int o = tid >> 5, lane = tid & 31;
            float a = 0.f;
#pragma unroll
            for (int kk = 0; kk < 4; ++kk) {
                const int k = lane + kk * 32;
                a = fmaf(s_h2[k], s_iW2[k * OUTD + o], a);
            }
#pragma unroll
            for (int off = 16; off; off >>= 1) a += __shfl_xor_sync(~0u, a, off);
            if (lane == 0) out[node * OUTD + o] = a + s_ib2[o];
        }
        __syncthreads();
    }
}

// ---------------------------------------------------------------------------
extern "C" void kernel_launch(void* const* d_in, const int* in_sizes, int n_in,
                              void* d_out, int out_size) {
    const float* x   = (const float*)d_in[0];
    const float* mW1 = (const float*)d_in[1];
    const float* mb1 = (const float*)d_in[2];
    const float* mW2 = (const float*)d_in[3];
    const float* mb2 = (const float*)d_in[4];
    const float* iW1 = (const float*)d_in[5];
    const float* ib1 = (const float*)d_in[6];
    const float* iW2 = (const float*)d_in[7];
    const float* ib2 = (const float*)d_in[8];
    float* out = (float*)d_out;

    kA<<<B_ * N_ / ABJ, HID>>>(x, mW1, mb1);          // 256 blocks

    dim3 gB(N_ / ITILE, B_, JSPLIT);                  // (64, 4, 4) = 1024 CTAs
    kB<<<gB, 256>>>(x, mW1);

    kC<<<B_ * N_ / NPB, HID>>>(x, mW2, mb2, iW1, ib1, iW2, ib2, out);
}

// round 3
// speedup vs baseline: 2.1649x; 1.2112x over previous
#include <cuda_runtime.h>

// Problem constants
#define B_    4
#define N_    512
#define T_    10
#define F_    516      // N + 4
#define HID   128
#define MSGD  32
#define UPDH  128
#define OUTD  4

// kB tiling
#define ITILE   8                   // i's per CTA
#define JSPLIT  4                   // j split across CTAs (blockIdx.z)
#define JCHUNK  (N_ / JSPLIT)       // 128 j per CTA
#define JGROUPS 4                   // j-groups per CTA (warp pairs)
#define JW      (JCHUNK / JGROUPS)  // 32 j per warp
#define KJ      4                   // j per staging round
#define RNDS    (JW / KJ)           // 8 rounds

// Scratch (static device arrays: no allocations allowed)
__device__ float g_C[B_ * N_ * HID];                 // C[b,j,hid], mb1 folded in
__device__ float g_part[JSPLIT * B_ * N_ * HID];     // partial H_sum per j-split

// ---------------------------------------------------------------------------
// packed fp32x2 helpers (sm_100+)
// ---------------------------------------------------------------------------
__device__ __forceinline__ float2 ffma2(float2 a, float2 b, float2 c) {
    float2 d;
    asm("fma.rn.f32x2 %0, %1, %2, %3;"
        : "=l"(reinterpret_cast<unsigned long long&>(d))
        : "l"(reinterpret_cast<unsigned long long&>(a)),
          "l"(reinterpret_cast<unsigned long long&>(b)),
          "l"(reinterpret_cast<unsigned long long&>(c)));
    return d;
}
__device__ __forceinline__ float2 fadd2(float2 a, float2 b) {
    float2 d;
    asm("add.rn.f32x2 %0, %1, %2;"
        : "=l"(reinterpret_cast<unsigned long long&>(d))
        : "l"(reinterpret_cast<unsigned long long&>(a)),
          "l"(reinterpret_cast<unsigned long long&>(b)));
    return d;
}

// ---------------------------------------------------------------------------
// Kernel A: C[b,j,hid] = mb1[hid] + sum_{t,k<4} x[b,j,t,k] * mW1[5t+k, hid]
// 1024 blocks x 128 threads; weights in 40 regs; 2 (b,j) per block.
// ---------------------------------------------------------------------------
#define ABJ 2
__global__ __launch_bounds__(128) void kA(const float* __restrict__ x,
                                          const float* __restrict__ mW1,
                                          const float* __restrict__ mb1) {
    const int hid = threadIdx.x;
    float w[40];
#pragma unroll
    for (int r = 0; r < 40; ++r)
        w[r] = mW1[(5 * (r >> 2) + (r & 3)) * HID + hid];
    const float bias = mb1[hid];

    __shared__ float sb[ABJ][40];
    const int bj0 = blockIdx.x * ABJ;
    if (hid < ABJ * 40) {
        const int nn = hid / 40, r = hid % 40;
        sb[nn][r] = x[((long)(bj0 + nn) * T_ + (r >> 2)) * F_ + (r & 3)];
    }
    __syncthreads();

#pragma unroll
    for (int nn = 0; nn < ABJ; ++nn) {
        float acc = bias;
#pragma unroll
        for (int r = 0; r < 40; ++r) acc = fmaf(sb[nn][r], w[r], acc);
        g_C[(long)(bj0 + nn) * HID + hid] = acc;
    }
}

// ---------------------------------------------------------------------------
// Kernel B (dominant):
//   H_sum[b,i,:] = sum_j relu( C[b,j,:] + sum_t e[b,j,t,i] * w_t[:] )
// CTA = (itile of 8 i, b, j-quarter). 256 threads.
// Warp = (hid-half hh, j-group jg): computes ALL 8 i x 64 hid for its 32 j.
// f32x2 packing over the i dimension: acc{i,i+1}, dup'd weights {w,w} in regs,
// e pairs {e(t,i),e(t,i+1)} read via broadcast LDS.64 from naturally-laid smem.
// No CTA barriers in mainloop; per-warp double-buffered smem + __syncwarp.
// ---------------------------------------------------------------------------
__global__ __launch_bounds__(256) void kB(const float* __restrict__ x,
                                          const float* __restrict__ mW1) {
    const int tid  = threadIdx.x;
    const int warp = tid >> 5, lane = tid & 31;
    const int hh   = warp & 1;               // hid half (0/1)
    const int jg   = warp >> 1;              // j-group 0..3
    const int itile = blockIdx.x;            // 0..63
    const int b     = blockIdx.y;            // 0..3
    const int js    = blockIdx.z;            // 0..3
    const int i0    = itile * ITILE;
    const int hid0  = hh * 64 + lane * 2;    // 2 hid per lane

    // Duplicated weights {w,w}: 2 hid x 10 t (loop-invariant, 40 regs)
    float2 wd0[T_], wd1[T_];
#pragma unroll
    for (int t = 0; t < T_; ++t) {
        float2 wv = *reinterpret_cast<const float2*>(&mW1[(5 * t + 4) * HID + hid0]);
        wd0[t] = make_float2(wv.x, wv.x);
        wd1[t] = make_float2(wv.y, wv.y);
    }

    // Per-warp e staging: [warp][buf][jj][t][i]  (natural loader layout)
    __shared__ __align__(16) float e_s[8][2][KJ][T_][ITILE];   // 20 KB
    __shared__ float red[JGROUPS][ITILE][HID];                 // 16 KB (epilogue)

    const int  jbase = js * JCHUNK + jg * JW;
    const bool ldr   = (lane < 2 * T_);                        // 20 loader lanes
    const int  lt    = lane >> 1;                              // t
    const int  lhf   = lane & 1;                               // i half (0/1)
    const long estr  = (long)T_ * F_;

    const float* egp = x + ((long)(b * N_ + jbase) * T_ + lt) * F_ + 4 + i0 + lhf * 4;
    const float* cgp = g_C + (long)(b * N_ + jbase) * HID + hid0;

    float4 eH[KJ];
    float2 cC[KJ], cH[KJ];

    // Prologue: round 0 staged, c(round 0) in cC
    if (ldr) {
#pragma unroll
        for (int jj = 0; jj < KJ; ++jj) eH[jj] = *reinterpret_cast<const float4*>(egp + (long)jj * estr);
#pragma unroll
        for (int jj = 0; jj < KJ; ++jj)
            *reinterpret_cast<float4*>(&e_s[warp][0][jj][lt][lhf * 4]) = eH[jj];
    }
#pragma unroll
    for (int jj = 0; jj < KJ; ++jj)
        cC[jj] = *reinterpret_cast<const float2*>(cgp + (long)jj * HID);
    __syncwarp();

    float2 acc[4][2];   // [i-pair][hid] of {i, i+1}
#pragma unroll
    for (int ip = 0; ip < 4; ++ip) {
        acc[ip][0] = make_float2(0.f, 0.f);
        acc[ip][1] = make_float2(0.f, 0.f);
    }

#pragma unroll 1
    for (int r = 0; r < RNDS; ++r) {
        const int cur = r & 1;

        // depth-1 prefetch of round r+1 (e into regs, c into cH)
        if (r + 1 < RNDS) {
            const long jb = (long)(r + 1) * KJ;
            if (ldr) {
#pragma unroll
                for (int jj = 0; jj < KJ; ++jj)
                    eH[jj] = *reinterpret_cast<const float4*>(egp + (jb + jj) * estr);
            }
#pragma unroll
            for (int jj = 0; jj < KJ; ++jj)
                cH[jj] = *reinterpret_cast<const float2*>(cgp + (jb + jj) * HID);
        }

        // ---- compute round r: KJ j's x 8 i x 2 hid ----
#pragma unroll
        for (int jj = 0; jj < KJ; ++jj) {
            const float2 cd0 = make_float2(cC[jj].x, cC[jj].x);
            const float2 cd1 = make_float2(cC[jj].y, cC[jj].y);
#pragma unroll
            for (int ip = 0; ip < 4; ++ip) {
                float2 p0 = cd0, p1 = cd1;
#pragma unroll
                for (int t = 0; t < T_; ++t) {
                    float2 e = *reinterpret_cast<const float2*>(&e_s[warp][cur][jj][t][2 * ip]);
                    p0 = ffma2(e, wd0[t], p0);
                    p1 = ffma2(e, wd1[t], p1);
                }
                acc[ip][0] = fadd2(acc[ip][0], make_float2(fmaxf(p0.x, 0.f), fmaxf(p0.y, 0.f)));
                acc[ip][1] = fadd2(acc[ip][1], make_float2(fmaxf(p1.x, 0.f), fmaxf(p1.y, 0.f)));
            }
        }

        __syncwarp();
        if (r + 1 < RNDS) {
            if (ldr) {
#pragma unroll
                for (int jj = 0; jj < KJ; ++jj)
                    *reinterpret_cast<float4*>(&e_s[warp][cur ^ 1][jj][lt][lhf * 4]) = eH[jj];
            }
#pragma unroll
            for (int jj = 0; jj < KJ; ++jj) cC[jj] = cH[jj];
        }
        __syncwarp();
    }

    // ---- epilogue: reduce the 4 j-groups in smem, store one slice ----
#pragma unroll
    for (int ip = 0; ip < 4; ++ip) {
#pragma unroll
        for (int h = 0; h < 2; ++h) {
            red[jg][2 * ip + 0][hid0 + h] = acc[ip][h].x;
            red[jg][2 * ip + 1][hid0 + h] = acc[ip][h].y;
        }
    }
    __syncthreads();

    {
        const int ii = tid >> 5;             // 0..7
        const int h4 = (tid & 31) * 4;       // 0..124
        float4 s = *reinterpret_cast<const float4*>(&red[0][ii][h4]);
#pragma unroll
        for (int g = 1; g < JGROUPS; ++g) {
            float4 v = *reinterpret_cast<const float4*>(&red[g][ii][h4]);
            s.x += v.x; s.y += v.y; s.z += v.z; s.w += v.w;
        }
        *reinterpret_cast<float4*>(
            &g_part[(long)js * (B_ * N_ * HID) + ((long)(b * N_ + i0 + ii)) * HID + h4]) = s;
    }
}

// ---------------------------------------------------------------------------
// Kernel C: per node — reduce j-split partials, apply mW2 (+ N*mb2),
// concat node_feat, 36 -> 128 (relu) -> 4 MLP. Block = 8 nodes, weights in smem.
// ---------------------------------------------------------------------------
#define NPB 8
__global__ __launch_bounds__(128) void kC(const float* __restrict__ x,
                                          const float* __restrict__ mW2,
                                          const float* __restrict__ mb2,
                                          const float* __restrict__ iW1,
                                          const float* __restrict__ ib1,
                                          const float* __restrict__ iW2,
                                          const float* __restrict__ ib2,
                                          float* __restrict__ out) {
    const int tid = threadIdx.x;

    __shared__ float s_mW2[HID * MSGD];          // 16 KB
    __shared__ float s_iW1[(MSGD + 4) * UPDH];   // 18 KB
    __shared__ float s_iW2[UPDH * OUTD];         // 2 KB
    __shared__ float s_mb2[MSGD], s_ib1[UPDH], s_ib2[OUTD];
    __shared__ float s_h[HID];
    __shared__ float s_red[4][MSGD];
    __shared__ float s_mi[MSGD + 4];
    __shared__ float s_h2[UPDH];
    __shared__ float s_nf[NPB][4];

    for (int i = tid; i < HID * MSGD; i += 128)        s_mW2[i] = mW2[i];
    for (int i = tid; i < (MSGD + 4) * UPDH; i += 128) s_iW1[i] = iW1[i];
    for (int i = tid; i < UPDH * OUTD; i += 128)       s_iW2[i] = iW2[i];
    if (tid < MSGD) s_mb2[tid] = mb2[tid];
    s_ib1[tid] = ib1[tid];
    if (tid < OUTD) s_ib2[tid] = ib2[tid];
    if (tid < NPB * 4) {
        const int nn = tid >> 2, k = tid & 3;
        s_nf[nn][k] = x[((long)(blockIdx.x * NPB + nn) * T_ + (T_ - 1)) * F_ + k];
    }
    __syncthreads();

    for (int nn = 0; nn < NPB; ++nn) {
        const long node = (long)blockIdx.x * NPB + nn;

        float h = 0.f;
#pragma unroll
        for (int p = 0; p < JSPLIT; ++p)
            h += g_part[(long)p * (B_ * N_ * HID) + node * HID + tid];
        s_h[tid] = h;
        __syncthreads();

        {   // mW2 GEMV split 4 ways over k
            const int m = tid & 31, seg = tid >> 5;
            float a = 0.f;
#pragma unroll
            for (int k2 = 0; k2 < 32; ++k2) {
                const int k = seg * 32 + k2;
                a = fmaf(s_h[k], s_mW2[k * MSGD + m], a);
            }
            s_red[seg][m] = a;
        }
        __syncthreads();
        if (tid < MSGD)
            s_mi[tid] = s_red[0][tid] + s_red[1][tid] + s_red[2][tid] + s_red[3][tid]
                      + (float)N_ * s_mb2[tid];
        if (tid < 4) s_mi[MSGD + tid] = s_nf[nn][tid];
        __syncthreads();

        {   // 36 -> 128 relu
            float a = s_ib1[tid];
#pragma unroll
            for (int k = 0; k < MSGD + 4; ++k)
                a = fmaf(s_mi[k], s_iW1[k * UPDH + tid], a);
            s_h2[tid] = fmaxf(a, 0.f);
        }
        __syncthreads();

        {   // 128 -> 4: warp o computes output o, shuffle-reduce
            const int o = tid >> 5, lane = tid & 31;
            float a = 0.f;
#pragma unroll
            for (int kk = 0; kk < 4; ++kk) {
                const int k = lane + kk * 32;
                a = fmaf(s_h2[k], s_iW2[k * OUTD + o], a);
            }
#pragma unroll
            for (int off = 16; off; off >>= 1) a += __shfl_xor_sync(~0u, a, off);
            if (lane == 0) out[node * OUTD + o] = a + s_ib2[o];
        }
        __syncthreads();
    }
}

// ---------------------------------------------------------------------------
extern "C" void kernel_launch(void* const* d_in, const int* in_sizes, int n_in,
                              void* d_out, int out_size) {
    const float* x   = (const float*)d_in[0];
    const float* mW1 = (const float*)d_in[1];
    const float* mb1 = (const float*)d_in[2];
    const float* mW2 = (const float*)d_in[3];
    const float* mb2 = (const float*)d_in[4];
    const float* iW1 = (const float*)d_in[5];
    const float* ib1 = (const float*)d_in[6];
    const float* iW2 = (const float*)d_in[7];
    const float* ib2 = (const float*)d_in[8];
    float* out = (float*)d_out;

    kA<<<B_ * N_ / ABJ, HID>>>(x, mW1, mb1);          // 1024 blocks

    dim3 gB(N_ / ITILE, B_, JSPLIT);                  // (64, 4, 4) = 1024 CTAs
    kB<<<gB, 256>>>(x, mW1);

    kC<<<B_ * N_ / NPB, HID>>>(x, mW2, mb2, iW1, ib1, iW2, ib2, out);
}